// round 3
// baseline (speedup 1.0000x reference)
#include <cuda_runtime.h>
#include <math.h>

#define MM 4096
#define DD 2048
#define INV_SQRT_M 0.015625f   // 1/sqrt(4096) exact

// ---------------- device scratch ----------------
__device__ float g_qt[MM];
__device__ float g_k[MM];
__device__ float g_v[MM];
__device__ float g_it, g_ft, g_ot;
__device__ float g_kqt, g_denom;

// ---------------- kernel 1: fused q/k/v matvecs + gates ----------------
// Warp-per-row: global warp gw < MM handles row gw of Wq,Wk,Wv.
// gw == MM handles the three gate rows Wi,Wf,Wo.
// Each lane: 16 float4 per matrix, in 4 batches of 12 front-batched __ldcs.
// Warp-shuffle reduction only — no smem, no __syncthreads.
__global__ __launch_bounds__(256) void mv_kernel(
    const float* __restrict__ x,
    const float* __restrict__ Wq, const float* __restrict__ bq,
    const float* __restrict__ Wk, const float* __restrict__ bk,
    const float* __restrict__ Wv, const float* __restrict__ bV,
    const float* __restrict__ Wi, const float* __restrict__ bi,
    const float* __restrict__ Wf, const float* __restrict__ bf,
    const float* __restrict__ Wo, const float* __restrict__ bo)
{
    const int gw   = blockIdx.x * 8 + (threadIdx.x >> 5);
    const int lane = threadIdx.x & 31;
    if (gw > MM) return;

    const bool gate = (gw == MM);
    const float *rA, *rB, *rC;
    if (!gate) {
        rA = Wq + (size_t)gw * DD;
        rB = Wk + (size_t)gw * DD;
        rC = Wv + (size_t)gw * DD;
    } else {
        rA = Wi; rB = Wf; rC = Wo;
    }

    const float4* A4 = reinterpret_cast<const float4*>(rA);
    const float4* B4 = reinterpret_cast<const float4*>(rB);
    const float4* C4 = reinterpret_cast<const float4*>(rC);
    const float4* x4 = reinterpret_cast<const float4*>(x);

    float sa = 0.f, sk = 0.f, sv = 0.f;
    // 512 float4 per row / 32 lanes = 16 per lane; batches of 4
    #pragma unroll
    for (int u = 0; u < 16; u += 4) {
        const int j0 = lane + (u + 0) * 32;
        const int j1 = lane + (u + 1) * 32;
        const int j2 = lane + (u + 2) * 32;
        const int j3 = lane + (u + 3) * 32;
        // 12 independent streaming loads front-batched
        float4 a0 = __ldcs(&A4[j0]); float4 a1 = __ldcs(&A4[j1]);
        float4 a2 = __ldcs(&A4[j2]); float4 a3 = __ldcs(&A4[j3]);
        float4 b0 = __ldcs(&B4[j0]); float4 b1 = __ldcs(&B4[j1]);
        float4 b2 = __ldcs(&B4[j2]); float4 b3 = __ldcs(&B4[j3]);
        float4 c0 = __ldcs(&C4[j0]); float4 c1 = __ldcs(&C4[j1]);
        float4 c2 = __ldcs(&C4[j2]); float4 c3 = __ldcs(&C4[j3]);
        float4 x0 = x4[j0]; float4 x1 = x4[j1];
        float4 x2 = x4[j2]; float4 x3 = x4[j3];

        sa += a0.x*x0.x + a0.y*x0.y + a0.z*x0.z + a0.w*x0.w
            + a1.x*x1.x + a1.y*x1.y + a1.z*x1.z + a1.w*x1.w
            + a2.x*x2.x + a2.y*x2.y + a2.z*x2.z + a2.w*x2.w
            + a3.x*x3.x + a3.y*x3.y + a3.z*x3.z + a3.w*x3.w;
        sk += b0.x*x0.x + b0.y*x0.y + b0.z*x0.z + b0.w*x0.w
            + b1.x*x1.x + b1.y*x1.y + b1.z*x1.z + b1.w*x1.w
            + b2.x*x2.x + b2.y*x2.y + b2.z*x2.z + b2.w*x2.w
            + b3.x*x3.x + b3.y*x3.y + b3.z*x3.z + b3.w*x3.w;
        sv += c0.x*x0.x + c0.y*x0.y + c0.z*x0.z + c0.w*x0.w
            + c1.x*x1.x + c1.y*x1.y + c1.z*x1.z + c1.w*x1.w
            + c2.x*x2.x + c2.y*x2.y + c2.z*x2.z + c2.w*x2.w
            + c3.x*x3.x + c3.y*x3.y + c3.z*x3.z + c3.w*x3.w;
    }

    #pragma unroll
    for (int o = 16; o > 0; o >>= 1) {
        sa += __shfl_down_sync(0xFFFFFFFFu, sa, o);
        sk += __shfl_down_sync(0xFFFFFFFFu, sk, o);
        sv += __shfl_down_sync(0xFFFFFFFFu, sv, o);
    }

    if (lane == 0) {
        if (!gate) {
            g_qt[gw] = sa + bq[gw];
            g_k[gw]  = INV_SQRT_M * (sk + bk[gw]);
            g_v[gw]  = sv + bV[gw];
        } else {
            g_it = expf(sa + bi[0]);
            g_ft = expf(sk + bf[0]);
            float z = sv + bo[0];
            g_ot = 1.0f / (1.0f + expf(-z));
        }
    }
}

// ---------------- kernel 2: n-update + tiny reductions ----------------
// n_i = ft*n_prev_i + it*k_i ; kqt = k·qt ; denom = max(|n·qt|, 1)
__global__ __launch_bounds__(1024) void nred_kernel(
    const float* __restrict__ n_prev, float* __restrict__ out_n)
{
    const int t = threadIdx.x;
    const float ft = g_ft, it = g_it;
    float kqt = 0.f, nqt = 0.f;
    #pragma unroll
    for (int u = 0; u < MM / 1024; u++) {
        int i = t + u * 1024;
        float k = g_k[i];
        float q = g_qt[i];
        kqt += k * q;
        float n = ft * n_prev[i] + it * k;
        out_n[i] = n;
        nqt += n * q;
    }
    #pragma unroll
    for (int o = 16; o > 0; o >>= 1) {
        kqt += __shfl_down_sync(0xFFFFFFFFu, kqt, o);
        nqt += __shfl_down_sync(0xFFFFFFFFu, nqt, o);
    }
    __shared__ float sk[32], sn[32];
    if ((t & 31) == 0) { sk[t >> 5] = kqt; sn[t >> 5] = nqt; }
    __syncthreads();
    if (t < 32) {
        float a = sk[t], b = sn[t];
        #pragma unroll
        for (int o = 16; o > 0; o >>= 1) {
            a += __shfl_down_sync(0xFFFFFFFFu, a, o);
            b += __shfl_down_sync(0xFFFFFFFFu, b, o);
        }
        if (t == 0) {
            g_kqt = a;
            g_denom = fmaxf(fabsf(b), 1.0f);
        }
    }
}

// ---------------- kernel 3: cp stream -> C write + cp@qt + ht ----------------
// Warp-per-row: each warp streams one 16KB row of cp in 4 batches of
// 8 front-batched __ldcs, writes C with __stcs, accumulates s_i = cp[i]·qt
// with a warp-only shuffle reduction, and lane 0 writes ht_i.
__global__ __launch_bounds__(256) void cp_kernel(
    const float* __restrict__ cp, float* __restrict__ outC,
    float* __restrict__ outH)
{
    const int i    = blockIdx.x * 8 + (threadIdx.x >> 5);
    const int lane = threadIdx.x & 31;

    const float ft  = g_ft;
    const float itv = g_it * g_v[i];

    const float4* cp4 = reinterpret_cast<const float4*>(cp   + (size_t)i * MM);
    float4*       Cw  = reinterpret_cast<float4*>(outC + (size_t)i * MM);
    const float4* k4  = reinterpret_cast<const float4*>(g_k);
    const float4* q4  = reinterpret_cast<const float4*>(g_qt);

    float s = 0.f;
    // 1024 float4 per row / 32 lanes = 32 per lane; batches of 8
    #pragma unroll
    for (int u = 0; u < 4; u++) {
        const int base = lane + u * 256;
        // 8 independent streaming loads front-batched
        float4 c0 = __ldcs(&cp4[base + 0 * 32]);
        float4 c1 = __ldcs(&cp4[base + 1 * 32]);
        float4 c2 = __ldcs(&cp4[base + 2 * 32]);
        float4 c3 = __ldcs(&cp4[base + 3 * 32]);
        float4 c4 = __ldcs(&cp4[base + 4 * 32]);
        float4 c5 = __ldcs(&cp4[base + 5 * 32]);
        float4 c6 = __ldcs(&cp4[base + 6 * 32]);
        float4 c7 = __ldcs(&cp4[base + 7 * 32]);

        #pragma unroll
        for (int j = 0; j < 8; j++) {
            float4 c;
            switch (j) {
                case 0: c = c0; break; case 1: c = c1; break;
                case 2: c = c2; break; case 3: c = c3; break;
                case 4: c = c4; break; case 5: c = c5; break;
                case 6: c = c6; break; default: c = c7; break;
            }
            const int idx = base + j * 32;
            float4 kk = k4[idx];
            float4 qq = q4[idx];
            float4 o;
            o.x = ft * c.x + itv * kk.x;
            o.y = ft * c.y + itv * kk.y;
            o.z = ft * c.z + itv * kk.z;
            o.w = ft * c.w + itv * kk.w;
            __stcs(&Cw[idx], o);
            s += c.x * qq.x + c.y * qq.y + c.z * qq.z + c.w * qq.w;
        }
    }

    #pragma unroll
    for (int o = 16; o > 0; o >>= 1) s += __shfl_down_sync(0xFFFFFFFFu, s, o);

    if (lane == 0) {
        outH[i] = (g_ot / g_denom) * (ft * s + itv * g_kqt);
    }
}

// ---------------- launch ----------------
extern "C" void kernel_launch(void* const* d_in, const int* in_sizes, int n_in,
                              void* d_out, int out_size)
{
    const float* x      = (const float*)d_in[0];
    const float* cp     = (const float*)d_in[1];
    const float* n_prev = (const float*)d_in[2];
    const float* Wq     = (const float*)d_in[3];
    const float* bq     = (const float*)d_in[4];
    const float* Wk     = (const float*)d_in[5];
    const float* bk     = (const float*)d_in[6];
    const float* Wv     = (const float*)d_in[7];
    const float* bV     = (const float*)d_in[8];
    const float* Wi     = (const float*)d_in[9];
    const float* bi     = (const float*)d_in[10];
    const float* Wf     = (const float*)d_in[11];
    const float* bf     = (const float*)d_in[12];
    const float* Wo     = (const float*)d_in[13];
    const float* bo     = (const float*)d_in[14];

    float* out  = (float*)d_out;
    float* outH = out;                        // ht: M
    float* outC = out + MM;                   // C : M*M
    float* outN = out + MM + (size_t)MM * MM; // n : M

    // 4096 rows + 1 gate warp: 513 blocks x 8 warps
    mv_kernel<<<513, 256>>>(x, Wq, bq, Wk, bk, Wv, bV,
                            Wi, bi, Wf, bf, Wo, bo);
    nred_kernel<<<1, 1024>>>(n_prev, outN);
    cp_kernel<<<MM / 8, 256>>>(cp, outC, outH);
}

// round 4
// speedup vs baseline: 1.1452x; 1.1452x over previous
#include <cuda_runtime.h>
#include <math.h>

#define MM 4096
#define DD 2048
#define INV_SQRT_M 0.015625f   // 1/sqrt(4096) exact

// ---------------- device scratch ----------------
__device__ float g_qt[MM];
__device__ float g_k[MM];
__device__ float g_v[MM];
__device__ float g_it, g_ft, g_ot;
__device__ float g_kqt, g_denom;

// ---------------- kernel 1: fused q/k/v matvecs + gates ----------------
// 512-thread blocks, 2 row-triples per block. Threads [0,256) handle row
// 2b, threads [256,512) handle row 2b+1. Per-thread: 6 front-batched
// streaming loads (2 float4 from each of Wq,Wk,Wv) + 2 cached x loads.
// Last block (b == MM/2) computes the three gates with its first half.
__global__ __launch_bounds__(512) void mv_kernel(
    const float* __restrict__ x,
    const float* __restrict__ Wq, const float* __restrict__ bq,
    const float* __restrict__ Wk, const float* __restrict__ bk,
    const float* __restrict__ Wv, const float* __restrict__ bV,
    const float* __restrict__ Wi, const float* __restrict__ bi,
    const float* __restrict__ Wf, const float* __restrict__ bf,
    const float* __restrict__ Wo, const float* __restrict__ bo)
{
    const int t    = threadIdx.x;
    const int half = t >> 8;          // 0 or 1
    const int tt   = t & 255;
    const int row  = blockIdx.x * 2 + half;
    const bool gate = (blockIdx.x == MM / 2);

    if (gate && half == 1) return;    // gate block uses first half only

    const float *rA, *rB, *rC;
    if (!gate) {
        rA = Wq + (size_t)row * DD;
        rB = Wk + (size_t)row * DD;
        rC = Wv + (size_t)row * DD;
    } else {
        rA = Wi; rB = Wf; rC = Wo;
    }

    const float4* A4 = reinterpret_cast<const float4*>(rA);
    const float4* B4 = reinterpret_cast<const float4*>(rB);
    const float4* C4 = reinterpret_cast<const float4*>(rC);
    const float4* x4 = reinterpret_cast<const float4*>(x);

    // 6 independent streaming loads, front-batched (MLP=6)
    float4 a0 = __ldcs(&A4[tt]);
    float4 a1 = __ldcs(&A4[tt + 256]);
    float4 k0 = __ldcs(&B4[tt]);
    float4 k1 = __ldcs(&B4[tt + 256]);
    float4 v0 = __ldcs(&C4[tt]);
    float4 v1 = __ldcs(&C4[tt + 256]);
    float4 x0 = x4[tt];
    float4 x1 = x4[tt + 256];

    float sa = a0.x * x0.x + a0.y * x0.y + a0.z * x0.z + a0.w * x0.w
             + a1.x * x1.x + a1.y * x1.y + a1.z * x1.z + a1.w * x1.w;
    float sk = k0.x * x0.x + k0.y * x0.y + k0.z * x0.z + k0.w * x0.w
             + k1.x * x1.x + k1.y * x1.y + k1.z * x1.z + k1.w * x1.w;
    float sv = v0.x * x0.x + v0.y * x0.y + v0.z * x0.z + v0.w * x0.w
             + v1.x * x1.x + v1.y * x1.y + v1.z * x1.z + v1.w * x1.w;

    #pragma unroll
    for (int o = 16; o > 0; o >>= 1) {
        sa += __shfl_down_sync(0xFFFFFFFFu, sa, o);
        sk += __shfl_down_sync(0xFFFFFFFFu, sk, o);
        sv += __shfl_down_sync(0xFFFFFFFFu, sv, o);
    }

    __shared__ float wsa[16], wsk[16], wsv[16];
    if ((t & 31) == 0) {
        int w = t >> 5;               // 0..7 for half 0, 8..15 for half 1
        wsa[w] = sa; wsk[w] = sk; wsv[w] = sv;
    }
    __syncthreads();
    // final 8-value reduce per half: lanes 0..7 of warp 0 (half 0) and
    // lanes 0..7 of warp 8 (half 1)
    if (tt < 8) {
        const int base = half * 8;
        float ra = wsa[base + tt], rk = wsk[base + tt], rv = wsv[base + tt];
        #pragma unroll
        for (int o = 4; o > 0; o >>= 1) {
            ra += __shfl_down_sync(0xFFu, ra, o, 8);
            rk += __shfl_down_sync(0xFFu, rk, o, 8);
            rv += __shfl_down_sync(0xFFu, rv, o, 8);
        }
        if (tt == 0) {
            if (!gate) {
                g_qt[row] = ra + bq[row];
                g_k[row]  = INV_SQRT_M * (rk + bk[row]);
                g_v[row]  = rv + bV[row];
            } else {
                g_it = expf(ra + bi[0]);
                g_ft = expf(rk + bf[0]);
                float z = rv + bo[0];
                g_ot = 1.0f / (1.0f + expf(-z));
            }
        }
    }
}

// ---------------- kernel 2: n-update + tiny reductions ----------------
// n_i = ft*n_prev_i + it*k_i ; kqt = k·qt ; denom = max(|n·qt|, 1)
__global__ __launch_bounds__(1024) void nred_kernel(
    const float* __restrict__ n_prev, float* __restrict__ out_n)
{
    const int t = threadIdx.x;
    const float ft = g_ft, it = g_it;
    float kqt = 0.f, nqt = 0.f;
    #pragma unroll
    for (int u = 0; u < MM / 1024; u++) {
        int i = t + u * 1024;
        float k = g_k[i];
        float q = g_qt[i];
        kqt += k * q;
        float n = ft * n_prev[i] + it * k;
        out_n[i] = n;
        nqt += n * q;
    }
    #pragma unroll
    for (int o = 16; o > 0; o >>= 1) {
        kqt += __shfl_down_sync(0xFFFFFFFFu, kqt, o);
        nqt += __shfl_down_sync(0xFFFFFFFFu, nqt, o);
    }
    __shared__ float sk[32], sn[32];
    if ((t & 31) == 0) { sk[t >> 5] = kqt; sn[t >> 5] = nqt; }
    __syncthreads();
    if (t < 32) {
        float a = sk[t], b = sn[t];
        #pragma unroll
        for (int o = 16; o > 0; o >>= 1) {
            a += __shfl_down_sync(0xFFFFFFFFu, a, o);
            b += __shfl_down_sync(0xFFFFFFFFu, b, o);
        }
        if (t == 0) {
            g_kqt = a;
            g_denom = fmaxf(fabsf(b), 1.0f);
        }
    }
}

// ---------------- kernel 3: cp stream -> C write + cp@qt + ht ----------------
// 4 rows per 512-thread block: each thread front-batches 8 independent
// streaming loads (2 float4 per row x 4 rows), writes C with __stcs,
// accumulates 4 per-row partial dots, one block reduce for all 4 rows.
__global__ __launch_bounds__(512) void cp_kernel(
    const float* __restrict__ cp, float* __restrict__ outC,
    float* __restrict__ outH)
{
    const int i0 = blockIdx.x * 4;
    const int t  = threadIdx.x;
    const float ft = g_ft;
    const float it = g_it;
    const float itv0 = it * g_v[i0 + 0];
    const float itv1 = it * g_v[i0 + 1];
    const float itv2 = it * g_v[i0 + 2];
    const float itv3 = it * g_v[i0 + 3];

    const float4* cpA = reinterpret_cast<const float4*>(cp + (size_t)(i0 + 0) * MM);
    const float4* cpB = reinterpret_cast<const float4*>(cp + (size_t)(i0 + 1) * MM);
    const float4* cpC = reinterpret_cast<const float4*>(cp + (size_t)(i0 + 2) * MM);
    const float4* cpD = reinterpret_cast<const float4*>(cp + (size_t)(i0 + 3) * MM);
    float4* CA = reinterpret_cast<float4*>(outC + (size_t)(i0 + 0) * MM);
    float4* CB = reinterpret_cast<float4*>(outC + (size_t)(i0 + 1) * MM);
    float4* CC = reinterpret_cast<float4*>(outC + (size_t)(i0 + 2) * MM);
    float4* CD = reinterpret_cast<float4*>(outC + (size_t)(i0 + 3) * MM);
    const float4* k4 = reinterpret_cast<const float4*>(g_k);
    const float4* q4 = reinterpret_cast<const float4*>(g_qt);

    const int j0 = t;
    const int j1 = t + 512;

    // 8 independent streaming loads front-batched (MLP=8)
    float4 cA0 = __ldcs(&cpA[j0]); float4 cA1 = __ldcs(&cpA[j1]);
    float4 cB0 = __ldcs(&cpB[j0]); float4 cB1 = __ldcs(&cpB[j1]);
    float4 cC0 = __ldcs(&cpC[j0]); float4 cC1 = __ldcs(&cpC[j1]);
    float4 cD0 = __ldcs(&cpD[j0]); float4 cD1 = __ldcs(&cpD[j1]);
    float4 ka = k4[j0], kb = k4[j1];
    float4 qa = q4[j0], qb = q4[j1];

    float4 o;
    o.x = ft*cA0.x + itv0*ka.x; o.y = ft*cA0.y + itv0*ka.y;
    o.z = ft*cA0.z + itv0*ka.z; o.w = ft*cA0.w + itv0*ka.w;
    __stcs(&CA[j0], o);
    o.x = ft*cA1.x + itv0*kb.x; o.y = ft*cA1.y + itv0*kb.y;
    o.z = ft*cA1.z + itv0*kb.z; o.w = ft*cA1.w + itv0*kb.w;
    __stcs(&CA[j1], o);
    o.x = ft*cB0.x + itv1*ka.x; o.y = ft*cB0.y + itv1*ka.y;
    o.z = ft*cB0.z + itv1*ka.z; o.w = ft*cB0.w + itv1*ka.w;
    __stcs(&CB[j0], o);
    o.x = ft*cB1.x + itv1*kb.x; o.y = ft*cB1.y + itv1*kb.y;
    o.z = ft*cB1.z + itv1*kb.z; o.w = ft*cB1.w + itv1*kb.w;
    __stcs(&CB[j1], o);
    o.x = ft*cC0.x + itv2*ka.x; o.y = ft*cC0.y + itv2*ka.y;
    o.z = ft*cC0.z + itv2*ka.z; o.w = ft*cC0.w + itv2*ka.w;
    __stcs(&CC[j0], o);
    o.x = ft*cC1.x + itv2*kb.x; o.y = ft*cC1.y + itv2*kb.y;
    o.z = ft*cC1.z + itv2*kb.z; o.w = ft*cC1.w + itv2*kb.w;
    __stcs(&CC[j1], o);
    o.x = ft*cD0.x + itv3*ka.x; o.y = ft*cD0.y + itv3*ka.y;
    o.z = ft*cD0.z + itv3*ka.z; o.w = ft*cD0.w + itv3*ka.w;
    __stcs(&CD[j0], o);
    o.x = ft*cD1.x + itv3*kb.x; o.y = ft*cD1.y + itv3*kb.y;
    o.z = ft*cD1.z + itv3*kb.z; o.w = ft*cD1.w + itv3*kb.w;
    __stcs(&CD[j1], o);

    float s0 = cA0.x*qa.x + cA0.y*qa.y + cA0.z*qa.z + cA0.w*qa.w
             + cA1.x*qb.x + cA1.y*qb.y + cA1.z*qb.z + cA1.w*qb.w;
    float s1 = cB0.x*qa.x + cB0.y*qa.y + cB0.z*qa.z + cB0.w*qa.w
             + cB1.x*qb.x + cB1.y*qb.y + cB1.z*qb.z + cB1.w*qb.w;
    float s2 = cC0.x*qa.x + cC0.y*qa.y + cC0.z*qa.z + cC0.w*qa.w
             + cC1.x*qb.x + cC1.y*qb.y + cC1.z*qb.z + cC1.w*qb.w;
    float s3 = cD0.x*qa.x + cD0.y*qa.y + cD0.z*qa.z + cD0.w*qa.w
             + cD1.x*qb.x + cD1.y*qb.y + cD1.z*qb.z + cD1.w*qb.w;

    #pragma unroll
    for (int o2 = 16; o2 > 0; o2 >>= 1) {
        s0 += __shfl_down_sync(0xFFFFFFFFu, s0, o2);
        s1 += __shfl_down_sync(0xFFFFFFFFu, s1, o2);
        s2 += __shfl_down_sync(0xFFFFFFFFu, s2, o2);
        s3 += __shfl_down_sync(0xFFFFFFFFu, s3, o2);
    }
    __shared__ float ws0[16], ws1[16], ws2[16], ws3[16];
    if ((t & 31) == 0) {
        int w = t >> 5;
        ws0[w] = s0; ws1[w] = s1; ws2[w] = s2; ws3[w] = s3;
    }
    __syncthreads();
    if (t < 16) {
        float a = ws0[t], b = ws1[t], c = ws2[t], d = ws3[t];
        #pragma unroll
        for (int o2 = 8; o2 > 0; o2 >>= 1) {
            a += __shfl_down_sync(0xFFFFu, a, o2, 16);
            b += __shfl_down_sync(0xFFFFu, b, o2, 16);
            c += __shfl_down_sync(0xFFFFu, c, o2, 16);
            d += __shfl_down_sync(0xFFFFu, d, o2, 16);
        }
        if (t == 0) {
            const float inv = g_ot / g_denom;
            const float kqt = g_kqt;
            outH[i0 + 0] = inv * (ft * a + itv0 * kqt);
            outH[i0 + 1] = inv * (ft * b + itv1 * kqt);
            outH[i0 + 2] = inv * (ft * c + itv2 * kqt);
            outH[i0 + 3] = inv * (ft * d + itv3 * kqt);
        }
    }
}

// ---------------- launch ----------------
extern "C" void kernel_launch(void* const* d_in, const int* in_sizes, int n_in,
                              void* d_out, int out_size)
{
    const float* x      = (const float*)d_in[0];
    const float* cp     = (const float*)d_in[1];
    const float* n_prev = (const float*)d_in[2];
    const float* Wq     = (const float*)d_in[3];
    const float* bq     = (const float*)d_in[4];
    const float* Wk     = (const float*)d_in[5];
    const float* bk     = (const float*)d_in[6];
    const float* Wv     = (const float*)d_in[7];
    const float* bV     = (const float*)d_in[8];
    const float* Wi     = (const float*)d_in[9];
    const float* bi     = (const float*)d_in[10];
    const float* Wf     = (const float*)d_in[11];
    const float* bf     = (const float*)d_in[12];
    const float* Wo     = (const float*)d_in[13];
    const float* bo     = (const float*)d_in[14];

    float* out  = (float*)d_out;
    float* outH = out;                        // ht: M
    float* outC = out + MM;                   // C : M*M
    float* outN = out + MM + (size_t)MM * MM; // n : M

    mv_kernel<<<MM / 2 + 1, 512>>>(x, Wq, bq, Wk, bk, Wv, bV,
                                   Wi, bi, Wf, bf, Wo, bo);
    nred_kernel<<<1, 1024>>>(n_prev, outN);
    cp_kernel<<<MM / 4, 512>>>(cp, outC, outH);
}